// round 5
// baseline (speedup 1.0000x reference)
#include <cuda_runtime.h>
#include <cstdint>

#define NN 20000
#define EE 320000
#define DD 128
#define KK 8
#define HH 64
#define KH 512   // K*H

// ---------------- scratch (static device arrays) ----------------------------
__device__ float g_mean[(size_t)EE * DD];          // mean features, CSR order
__device__ float g_ex[(size_t)EE * KK];            // exp(logits), CSR order
__device__ float g_er[(size_t)NN * KK];            // node_feat @ W_r^T
__device__ float g_W2[KK * DD];                    // [k][d] reduced weights
__device__ float g_S[(size_t)NN * KK * DD];        // aggregated, normalized
__device__ int   g_cnt[NN];
__device__ int   g_off[NN + 1];
__device__ int   g_cur[NN];
__device__ int   g_pos[EE];                        // edge -> CSR slot

// ---------------- setup ------------------------------------------------------
__global__ void zero_cnt_kernel() {
    int i = blockIdx.x * blockDim.x + threadIdx.x;
    if (i < NN) g_cnt[i] = 0;
}

// W2[k][d] = sum_h W_enc[d, k*H+h] * attn_l[k*H+h]
__global__ void w2_kernel(const float* __restrict__ W_enc,
                          const float* __restrict__ attn_l) {
    int t = blockIdx.x * blockDim.x + threadIdx.x;
    if (t >= KK * DD) return;
    int d = t >> 3, k = t & 7;
    float s = 0.0f;
#pragma unroll 8
    for (int h = 0; h < HH; h++)
        s += W_enc[(size_t)d * KH + k * HH + h] * attn_l[k * HH + h];
    g_W2[k * DD + d] = s;
}

// ---------------- er[n][k] = dot(node_feat[n], W_r[k]) ----------------------
__global__ void er_kernel(const float* __restrict__ nf, const float* __restrict__ Wr) {
    int warp = (blockIdx.x * blockDim.x + threadIdx.x) >> 5;
    int lane = threadIdx.x & 31;
    if (warp >= NN) return;
    float4 x = *(const float4*)(nf + (size_t)warp * DD + lane * 4);
#pragma unroll
    for (int k = 0; k < KK; k++) {
        float4 w = *(const float4*)(Wr + (size_t)k * DD + lane * 4);
        float p = x.x * w.x + x.y * w.y + x.z * w.z + x.w * w.w;
#pragma unroll
        for (int off = 16; off > 0; off >>= 1) p += __shfl_xor_sync(0xffffffffu, p, off);
        if (lane == 0) g_er[(size_t)warp * KK + k] = p;
    }
}

// ---------------- CSR build --------------------------------------------------
__global__ void hist_kernel(const int* __restrict__ dst) {
    int e = blockIdx.x * blockDim.x + threadIdx.x;
    if (e < EE) atomicAdd(&g_cnt[dst[e]], 1);
}

__global__ void scan_kernel() {   // single block, 1024 threads, 20 counts each
    __shared__ int part[1024];
    int t = threadIdx.x;
    int base = t * 20;
    int loc[20];
    int s = 0;
#pragma unroll
    for (int i = 0; i < 20; i++) {
        int idx = base + i;
        int c = (idx < NN) ? g_cnt[idx] : 0;
        loc[i] = s;
        s += c;
    }
    part[t] = s;
    __syncthreads();
    for (int off = 1; off < 1024; off <<= 1) {
        int v = (t >= off) ? part[t - off] : 0;
        __syncthreads();
        part[t] += v;
        __syncthreads();
    }
    int excl = (t == 0) ? 0 : part[t - 1];
#pragma unroll
    for (int i = 0; i < 20; i++) {
        int idx = base + i;
        if (idx < NN) {
            g_off[idx] = excl + loc[i];
            g_cur[idx] = excl + loc[i];
        }
    }
    if (t == 1023) g_off[NN] = part[1023];
}

__global__ void fill_kernel(const int* __restrict__ dst) {
    int e = blockIdx.x * blockDim.x + threadIdx.x;
    if (e < EE) {
        int p = atomicAdd(&g_cur[dst[e]], 1);
        g_pos[e] = p;
    }
}

// ---------------- mean + logits + exp (one warp per edge, CSR-ordered out) ---
__global__ __launch_bounds__(256) void mean_logits_kernel(
    const float* __restrict__ ef, const int* __restrict__ dst) {
    __shared__ float w2s[KK * DD];
    int t = threadIdx.x;
    for (int i = t; i < KK * DD; i += 256) w2s[i] = g_W2[i];
    __syncthreads();

    int warp = blockIdx.x * 8 + (t >> 5);   // EE/8 blocks, always full
    int lane = t & 31;
    int p = g_pos[warp];                    // broadcast load per warp

    size_t base = (size_t)warp * 3 * DD + lane * 4;
    float4 a = *(const float4*)(ef + base);
    float4 b = *(const float4*)(ef + base + DD);
    float4 c = *(const float4*)(ef + base + 2 * DD);
    const float s = 1.0f / 3.0f;
    float4 m;
    m.x = (a.x + b.x + c.x) * s;
    m.y = (a.y + b.y + c.y) * s;
    m.z = (a.z + b.z + c.z) * s;
    m.w = (a.w + b.w + c.w) * s;
    *(float4*)(g_mean + (size_t)p * DD + lane * 4) = m;

    float pk[KK];
#pragma unroll
    for (int k = 0; k < KK; k++) {
        float4 w = *(const float4*)(w2s + k * DD + lane * 4);
        pk[k] = m.x * w.x + m.y * w.y + m.z * w.z + m.w * w.w;
    }
#pragma unroll
    for (int off = 16; off > 0; off >>= 1)
#pragma unroll
        for (int k = 0; k < KK; k++) pk[k] += __shfl_xor_sync(0xffffffffu, pk[k], off);

    if (lane == 0) {
        int d = dst[warp];
        float4 er0 = *(const float4*)(g_er + (size_t)d * KK);
        float4 er1 = *(const float4*)(g_er + (size_t)d * KK + 4);
        float erv[8] = {er0.x, er0.y, er0.z, er0.w, er1.x, er1.y, er1.z, er1.w};
        float exv[8];
#pragma unroll
        for (int k = 0; k < KK; k++) {
            float v = pk[k] + erv[k];
            v = (v > 0.0f) ? v : 0.01f * v;
            exv[k] = expf(v);
        }
        *(float4*)(g_ex + (size_t)p * KK) = make_float4(exv[0], exv[1], exv[2], exv[3]);
        *(float4*)(g_ex + (size_t)p * KK + 4) = make_float4(exv[4], exv[5], exv[6], exv[7]);
    }
}

// ---------------- per-node gather-aggregate (contiguous CSR reads) -----------
// block = node; thread t: k = t>>5, d4 = t&31 owns S[n][k][d4*4..+3]
#define BATCH 16
__global__ __launch_bounds__(256) void aggregate_kernel() {
    __shared__ float ms[BATCH][DD];
    __shared__ float exs[BATCH][KK];
    int n = blockIdx.x;
    int t = threadIdx.x;
    int k = t >> 5, d4 = t & 31;
    int beg = g_off[n], end = g_off[n + 1];

    float4 acc = make_float4(0.f, 0.f, 0.f, 0.f);
    float exsum = 0.0f;

    for (int p0 = beg; p0 < end; p0 += BATCH) {
        int nb = end - p0;
        if (nb > BATCH) nb = BATCH;
        // coalesced stream copy: nb rows of 128 floats, contiguous in g_mean
        const float4* src = (const float4*)(g_mean + (size_t)p0 * DD);
        int tot4 = nb * (DD / 4);
        for (int i = t; i < tot4; i += 256) ((float4*)ms)[i] = src[i];
        const float* esrc = g_ex + (size_t)p0 * KK;
        if (t < nb * KK) ((float*)exs)[t] = esrc[t];
        __syncthreads();
#pragma unroll 4
        for (int j = 0; j < nb; j++) {
            float ev = exs[j][k];
            float4 mv = *(const float4*)&ms[j][d4 * 4];
            acc.x += ev * mv.x; acc.y += ev * mv.y;
            acc.z += ev * mv.z; acc.w += ev * mv.w;
            exsum += ev;
        }
        __syncthreads();
    }
    float scale = (exsum > 0.0f) ? (1.0f / exsum) : 0.0f;
    acc.x *= scale; acc.y *= scale; acc.z *= scale; acc.w *= scale;
    *(float4*)(g_S + ((size_t)n * KK + k) * DD + d4 * 4) = acc;
}

// ---------------- final small GEMM: out[n,k,:] = S[n,k,:] @ W_enc[:,kH:kH+H] -
// block: 64 nodes x 1 head; 256 threads as 16x16, 4x4 microtile
#define CP 132   // S smem stride (16B-aligned rows, 4-bank shift)
#define WP 65    // W smem stride
#define SMEM_C ((64 * CP + DD * WP) * 4)
__global__ __launch_bounds__(256) void out_gemm_kernel(
    const float* __restrict__ W_enc, float* __restrict__ out) {
    extern __shared__ float smc[];
    float* Ss = smc;              // [64][CP]
    float* Ws = smc + 64 * CP;    // [DD][WP]

    int t = threadIdx.x;
    int n0 = blockIdx.x * 64;
    int k = blockIdx.y;

    // load W tile: W_enc[d][k*64+h]
#pragma unroll
    for (int i = 0; i < 32; i++) {
        int idx = i * 256 + t;         // 8192
        int d = idx >> 6, h = idx & 63;
        Ws[d * WP + h] = W_enc[(size_t)d * KH + k * HH + h];
    }
    // load S tile: rows n0..n0+63 (float4)
#pragma unroll
    for (int i = 0; i < 8; i++) {
        int idx = i * 256 + t;         // 2048 float4s
        int r = idx >> 5, c4 = idx & 31;
        int n = n0 + r;
        float4 v = (n < NN)
            ? *(const float4*)(g_S + ((size_t)n * KK + k) * DD + c4 * 4)
            : make_float4(0.f, 0.f, 0.f, 0.f);
        *(float4*)(Ss + r * CP + c4 * 4) = v;
    }
    __syncthreads();

    int tx = t & 15, ty = t >> 4;
    float c[4][4];
#pragma unroll
    for (int i = 0; i < 4; i++)
#pragma unroll
        for (int j = 0; j < 4; j++) c[i][j] = 0.0f;

#pragma unroll 8
    for (int d = 0; d < DD; d++) {
        float av[4], bv[4];
#pragma unroll
        for (int i = 0; i < 4; i++) av[i] = Ss[(ty * 4 + i) * CP + d];
#pragma unroll
        for (int j = 0; j < 4; j++) bv[j] = Ws[d * WP + tx * 4 + j];
#pragma unroll
        for (int i = 0; i < 4; i++)
#pragma unroll
            for (int j = 0; j < 4; j++) c[i][j] += av[i] * bv[j];
    }

#pragma unroll
    for (int i = 0; i < 4; i++) {
        int n = n0 + ty * 4 + i;
        if (n < NN) {
            *(float4*)(out + (size_t)n * KH + k * HH + tx * 4) =
                make_float4(c[i][0], c[i][1], c[i][2], c[i][3]);
        }
    }
}

// ---------------- launch -----------------------------------------------------
extern "C" void kernel_launch(void* const* d_in, const int* in_sizes, int n_in,
                              void* d_out, int out_size) {
    const float* node_feat = (const float*)d_in[0];   // (N,128)
    const float* edge_feat = (const float*)d_in[1];   // (E,3,128)
    const float* W_enc     = (const float*)d_in[2];   // (128,512)
    const float* attn_l    = (const float*)d_in[3];   // (1,8,64)
    const float* W_r       = (const float*)d_in[4];   // (8,128)
    const int*   dst       = (const int*)d_in[5];     // (E,)
    float* out = (float*)d_out;                       // (N,8,64)

    cudaFuncSetAttribute(out_gemm_kernel,
                         cudaFuncAttributeMaxDynamicSharedMemorySize, SMEM_C);

    zero_cnt_kernel<<<(NN + 255) / 256, 256>>>();
    w2_kernel<<<4, 256>>>(W_enc, attn_l);
    er_kernel<<<NN / 8, 256>>>(node_feat, W_r);
    hist_kernel<<<EE / 256, 256>>>(dst);
    scan_kernel<<<1, 1024>>>();
    fill_kernel<<<EE / 256, 256>>>(dst);
    mean_logits_kernel<<<EE / 8, 256>>>(edge_feat, dst);
    aggregate_kernel<<<NN, 256>>>();
    out_gemm_kernel<<<dim3((NN + 63) / 64, KK), 256, SMEM_C>>>(W_enc, out);
}

// round 7
// speedup vs baseline: 1.0060x; 1.0060x over previous
#include <cuda_runtime.h>
#include <cstdint>

#define NN 20000
#define EE 320000
#define DD 128
#define KK 8
#define HH 64
#define KH 512   // K*H

// ---------------- scratch (static device arrays) ----------------------------
__device__ float g_mean[(size_t)EE * DD];          // 164 MB mean features (e-order)
__device__ float g_ex[(size_t)EE * KK];            // exp(logits)
__device__ float g_er[(size_t)NN * KK];            // node_feat @ W_r^T
__device__ float g_W2[KK * DD];                    // [k][d] reduced weights
__device__ float g_S[(size_t)NN * KK * DD];        // aggregated, normalized
__device__ int   g_cnt[NN];
__device__ int   g_off[NN + 1];
__device__ int   g_cur[NN];
__device__ int   g_list[EE];

// ---------------- prep: zero counts + W2 + er in one launch ------------------
// blocks [0,79): zero g_cnt ; [79,83): W2 ; [83,2583): er
__global__ __launch_bounds__(256) void prep_kernel(
    const float* __restrict__ nf, const float* __restrict__ Wr,
    const float* __restrict__ W_enc, const float* __restrict__ attn_l) {
    int b = blockIdx.x;
    int t = threadIdx.x;
    if (b < 79) {
        int i = b * 256 + t;
        if (i < NN) g_cnt[i] = 0;
    } else if (b < 83) {
        int idx = (b - 79) * 256 + t;
        if (idx < KK * DD) {
            int d = idx >> 3, k = idx & 7;
            float s = 0.0f;
#pragma unroll 8
            for (int h = 0; h < HH; h++)
                s += W_enc[(size_t)d * KH + k * HH + h] * attn_l[k * HH + h];
            g_W2[k * DD + d] = s;
        }
    } else {
        int warp = (b - 83) * 8 + (t >> 5);
        int lane = t & 31;
        if (warp >= NN) return;
        float4 x = *(const float4*)(nf + (size_t)warp * DD + lane * 4);
#pragma unroll
        for (int k = 0; k < KK; k++) {
            float4 w = *(const float4*)(Wr + (size_t)k * DD + lane * 4);
            float p = x.x * w.x + x.y * w.y + x.z * w.z + x.w * w.w;
#pragma unroll
            for (int off = 16; off > 0; off >>= 1)
                p += __shfl_xor_sync(0xffffffffu, p, off);
            if (lane == 0) g_er[(size_t)warp * KK + k] = p;
        }
    }
}

// ---------------- CSR build --------------------------------------------------
__global__ void hist_kernel(const int* __restrict__ dst) {
    int e = blockIdx.x * blockDim.x + threadIdx.x;
    if (e < EE) atomicAdd(&g_cnt[dst[e]], 1);
}

__global__ void scan_kernel() {   // single block, 1024 threads, 20 counts each
    __shared__ int part[1024];
    int t = threadIdx.x;
    int base = t * 20;
    int loc[20];
    int s = 0;
#pragma unroll
    for (int i = 0; i < 20; i++) {
        int idx = base + i;
        int c = (idx < NN) ? g_cnt[idx] : 0;
        loc[i] = s;
        s += c;
    }
    part[t] = s;
    __syncthreads();
    for (int off = 1; off < 1024; off <<= 1) {
        int v = (t >= off) ? part[t - off] : 0;
        __syncthreads();
        part[t] += v;
        __syncthreads();
    }
    int excl = (t == 0) ? 0 : part[t - 1];
#pragma unroll
    for (int i = 0; i < 20; i++) {
        int idx = base + i;
        if (idx < NN) {
            g_off[idx] = excl + loc[i];
            g_cur[idx] = excl + loc[i];
        }
    }
    if (t == 1023) g_off[NN] = part[1023];
}

__global__ void fill_kernel(const int* __restrict__ dst) {
    int e = blockIdx.x * blockDim.x + threadIdx.x;
    if (e < EE) {
        int p = atomicAdd(&g_cur[dst[e]], 1);
        g_list[p] = e;
    }
}

// ---------------- mean + logits + exp (one warp per edge, e-order out) -------
__global__ __launch_bounds__(256) void mean_logits_kernel(
    const float* __restrict__ ef, const int* __restrict__ dst) {
    __shared__ float w2s[KK * DD];
    int t = threadIdx.x;
    for (int i = t; i < KK * DD; i += 256) w2s[i] = g_W2[i];
    __syncthreads();

    int warp = blockIdx.x * 8 + (t >> 5);   // EE/8 blocks, always full
    int lane = t & 31;

    size_t base = (size_t)warp * 3 * DD + lane * 4;
    float4 a = *(const float4*)(ef + base);
    float4 b = *(const float4*)(ef + base + DD);
    float4 c = *(const float4*)(ef + base + 2 * DD);
    const float s = 1.0f / 3.0f;
    float4 m;
    m.x = (a.x + b.x + c.x) * s;
    m.y = (a.y + b.y + c.y) * s;
    m.z = (a.z + b.z + c.z) * s;
    m.w = (a.w + b.w + c.w) * s;
    *(float4*)(g_mean + (size_t)warp * DD + lane * 4) = m;

    float pk[KK];
#pragma unroll
    for (int k = 0; k < KK; k++) {
        float4 w = *(const float4*)(w2s + k * DD + lane * 4);
        pk[k] = m.x * w.x + m.y * w.y + m.z * w.z + m.w * w.w;
    }
#pragma unroll
    for (int off = 16; off > 0; off >>= 1)
#pragma unroll
        for (int k = 0; k < KK; k++) pk[k] += __shfl_xor_sync(0xffffffffu, pk[k], off);

    if (lane == 0) {
        int d = dst[warp];
        float4 er0 = *(const float4*)(g_er + (size_t)d * KK);
        float4 er1 = *(const float4*)(g_er + (size_t)d * KK + 4);
        float erv[8] = {er0.x, er0.y, er0.z, er0.w, er1.x, er1.y, er1.z, er1.w};
        float exv[8];
#pragma unroll
        for (int k = 0; k < KK; k++) {
            float v = pk[k] + erv[k];
            v = (v > 0.0f) ? v : 0.01f * v;
            exv[k] = expf(v);
        }
        *(float4*)(g_ex + (size_t)warp * KK) = make_float4(exv[0], exv[1], exv[2], exv[3]);
        *(float4*)(g_ex + (size_t)warp * KK + 4) = make_float4(exv[4], exv[5], exv[6], exv[7]);
    }
}

// ---------------- per-node gather-aggregate (warp = head, no barriers) -------
__global__ __launch_bounds__(256) void aggregate_kernel() {
    int n = blockIdx.x;
    int k = threadIdx.x >> 5;     // head
    int lane = threadIdx.x & 31;  // 4 dims per lane (float4 = 16B, coalesced row)
    int beg = g_off[n], end = g_off[n + 1];

    float4 acc = make_float4(0.f, 0.f, 0.f, 0.f);
    float exsum = 0.0f;

    for (int c = beg; c < end; c += 32) {
        int nb = end - c;
        if (nb > 32) nb = 32;
        int e_l = 0;
        float ex_l = 0.0f;
        if (lane < nb) {
            e_l = g_list[c + lane];
            ex_l = g_ex[(size_t)e_l * KK + k];
        }
#pragma unroll 4
        for (int j = 0; j < nb; j++) {
            int e = __shfl_sync(0xffffffffu, e_l, j);
            float ev = __shfl_sync(0xffffffffu, ex_l, j);
            float4 mv = *(const float4*)(g_mean + (size_t)e * DD + lane * 4);
            acc.x += ev * mv.x; acc.y += ev * mv.y;
            acc.z += ev * mv.z; acc.w += ev * mv.w;
            exsum += ev;
        }
    }
    float scale = (exsum > 0.0f) ? (1.0f / exsum) : 0.0f;
    acc.x *= scale; acc.y *= scale; acc.z *= scale; acc.w *= scale;
    *(float4*)(g_S + ((size_t)n * KK + k) * DD + lane * 4) = acc;
}

// ---------------- final small GEMM: out[n,k,:] = S[n,k,:] @ W_enc[:,kH:kH+H] -
#define CP 132   // S smem stride (16B-aligned rows, 4-bank shift)
#define WP 65    // W smem stride
#define SMEM_C ((64 * CP + DD * WP) * 4)
__global__ __launch_bounds__(256) void out_gemm_kernel(
    const float* __restrict__ W_enc, float* __restrict__ out) {
    extern __shared__ float smc[];
    float* Ss = smc;              // [64][CP]
    float* Ws = smc + 64 * CP;    // [DD][WP]

    int t = threadIdx.x;
    int n0 = blockIdx.x * 64;
    int k = blockIdx.y;

#pragma unroll
    for (int i = 0; i < 32; i++) {
        int idx = i * 256 + t;         // 8192
        int d = idx >> 6, h = idx & 63;
        Ws[d * WP + h] = W_enc[(size_t)d * KH + k * HH + h];
    }
#pragma unroll
    for (int i = 0; i < 8; i++) {
        int idx = i * 256 + t;         // 2048 float4s
        int r = idx >> 5, c4 = idx & 31;
        int n = n0 + r;
        float4 v = (n < NN)
            ? *(const float4*)(g_S + ((size_t)n * KK + k) * DD + c4 * 4)
            : make_float4(0.f, 0.f, 0.f, 0.f);
        *(float4*)(Ss + r * CP + c4 * 4) = v;
    }
    __syncthreads();

    int tx = t & 15, ty = t >> 4;
    float c[4][4];
#pragma unroll
    for (int i = 0; i < 4; i++)
#pragma unroll
        for (int j = 0; j < 4; j++) c[i][j] = 0.0f;

#pragma unroll 8
    for (int d = 0; d < DD; d++) {
        float av[4], bv[4];
#pragma unroll
        for (int i = 0; i < 4; i++) av[i] = Ss[(ty * 4 + i) * CP + d];
#pragma unroll
        for (int j = 0; j < 4; j++) bv[j] = Ws[d * WP + tx * 4 + j];
#pragma unroll
        for (int i = 0; i < 4; i++)
#pragma unroll
            for (int j = 0; j < 4; j++) c[i][j] += av[i] * bv[j];
    }

#pragma unroll
    for (int i = 0; i < 4; i++) {
        int n = n0 + ty * 4 + i;
        if (n < NN) {
            *(float4*)(out + (size_t)n * KH + k * HH + tx * 4) =
                make_float4(c[i][0], c[i][1], c[i][2], c[i][3]);
        }
    }
}

// ---------------- launch -----------------------------------------------------
extern "C" void kernel_launch(void* const* d_in, const int* in_sizes, int n_in,
                              void* d_out, int out_size) {
    const float* node_feat = (const float*)d_in[0];   // (N,128)
    const float* edge_feat = (const float*)d_in[1];   // (E,3,128)
    const float* W_enc     = (const float*)d_in[2];   // (128,512)
    const float* attn_l    = (const float*)d_in[3];   // (1,8,64)
    const float* W_r       = (const float*)d_in[4];   // (8,128)
    const int*   dst       = (const int*)d_in[5];     // (E,)
    float* out = (float*)d_out;                       // (N,8,64)

    cudaFuncSetAttribute(out_gemm_kernel,
                         cudaFuncAttributeMaxDynamicSharedMemorySize, SMEM_C);

    prep_kernel<<<2583, 256>>>(node_feat, W_r, W_enc, attn_l);
    hist_kernel<<<EE / 256, 256>>>(dst);
    scan_kernel<<<1, 1024>>>();
    fill_kernel<<<EE / 256, 256>>>(dst);
    mean_logits_kernel<<<EE / 8, 256>>>(edge_feat, dst);
    aggregate_kernel<<<NN, 256>>>();
    out_gemm_kernel<<<dim3((NN + 63) / 64, KK), 256, SMEM_C>>>(W_enc, out);
}